// round 11
// baseline (speedup 1.0000x reference)
#include <cuda_runtime.h>
#include <cuda_fp16.h>
#include <cstdint>

// ---------------------------------------------------------------------------
// XORConv2d: out = conv_valid(x, 1-2W), x (32,128,64,64) f32, W (256,128,3,3)
// Implicit GEMM on mma.sync fp16/fp32. sm_103 plain target (no tcgen05).
// R11: R7 mainloop VERBATIM (measured best: 64x32 warp tile, 124px CTA tile,
// load_A before frags) + single merged prep launch (from R9).
// ---------------------------------------------------------------------------

#define BDIM   32
#define CIN    128
#define HH     64
#define WWID   64
#define COUT   256
#define HOUT   62
#define WOUT   62
#define PIX_PER_IMG (HOUT*WOUT)         // 3844

__device__ __half g_x[(size_t)BDIM * HH * WWID * CIN];   // NHWC fp16, 32 MB
__device__ __half g_w[9 * COUT * CIN];                   // (1-2W), [kp][co][cin]

static __device__ __forceinline__ uint32_t smem_u32(const void* p) {
    uint32_t a;
    asm("{ .reg .u64 t; cvta.to.shared.u64 t, %1; cvt.u32.u64 %0, t; }"
        : "=r"(a) : "l"(p));
    return a;
}

// ---------------------------------------------------------------------------
// Merged prep: blocks [0,8192) transpose x NCHW f32 -> NHWC f16 (full-sector
// packed half2 writes); blocks [8192, 8192+1152) build g_w = 1-2W.
// ---------------------------------------------------------------------------
#define XBLOCKS 8192
#define WBLOCKS ((COUT*CIN*9 + 255) / 256)    // 1152

__global__ void prep_all(const float* __restrict__ x,
                         const float* __restrict__ W) {
    if (blockIdx.x < XBLOCKS) {
        __shared__ float t[64][33];
        int bid = blockIdx.x;
        int bh  = bid & 2047;              // b*64 + h
        int rest = bid >> 11;              // 0..3
        int b  = bh >> 6, h = bh & 63;
        int c0 = (rest & 1) * 64;
        int w0 = (rest >> 1) * 32;
        int l  = threadIdx.x & 31, wy = threadIdx.x >> 5;   // 8 warps

        const float* src = x + ((size_t)(b * CIN + c0)) * (HH * WWID)
                             + h * WWID + w0;
#pragma unroll
        for (int i = 0; i < 8; i++)
            t[wy + 8 * i][l] = src[(size_t)(wy + 8 * i) * (HH * WWID) + l];
        __syncthreads();

#pragma unroll
        for (int i = 0; i < 4; i++) {
            int ww = wy + 8 * i;
            __half2 v = __floats2half2_rn(t[2 * l][ww], t[2 * l + 1][ww]);
            __half* drow = g_x + ((size_t)(bh * WWID) + w0 + ww) * CIN + c0;
            ((uint32_t*)drow)[l] = *(uint32_t*)&v;
        }
    } else {
        int idx = (blockIdx.x - XBLOCKS) * 256 + threadIdx.x;
        if (idx < COUT * CIN * 9) {
            int co  = idx / (CIN * 9);
            int r   = idx - co * (CIN * 9);
            int cin = r / 9;
            int kp  = r - cin * 9;
            g_w[(kp * COUT + co) * CIN + cin] =
                __float2half_rn(1.0f - 2.0f * W[idx]);
        }
    }
}

// ---------------------------------------------------------------------------
// Main (R7 verbatim): CTA = 256 co x 124 pixels (image b, rows r0, r0+1).
// Patch = input rows r0..r0+3 (256 rows x 256B = 64KB), loaded once.
// A double-buffered over 9 kp, one barrier per kp; register frag dbuf.
// 16 warps: 4(M) x 4(N), warp tile 64x32. grid (31, 32), 512 threads.
// ---------------------------------------------------------------------------
#define ASTAGE 65536
#define SMEM_BYTES (2*65536 + 65536 + 2048)

__global__ void __launch_bounds__(512, 1)
xorconv_main(float* __restrict__ out) {
    extern __shared__ char smem[];
    const uint32_t sb = smem_u32(smem);
    const uint32_t PB = sb + 2 * ASTAGE;        // patch base

    const int tid = threadIdx.x;
    const int l   = tid & 31;
    const int w   = tid >> 5;          // 0..15
    const int wm  = w & 3;             // M group (64 co)
    const int wn  = w >> 2;            // N group (32 pix)
    const int b   = blockIdx.y;
    const int r0  = blockIdx.x * 2;    // first output row

    const int c    = tid & 15;         // 16B chunk in a 256B row
    const int rgrp = tid >> 4;         // 32 groups; rows r = rgrp + 32*i

    // Patch: 256 contiguous g_x rows starting at (b, r0, 0)
    {
        const __half* xsrc = g_x + ((size_t)(b * (HH * WWID) + r0 * WWID)) * CIN;
#pragma unroll
        for (int i = 0; i < 8; i++) {
            int r = rgrp + 32 * i;
            uint32_t sw = (uint32_t)r * 256u + (uint32_t)((c ^ (r & 7)) * 16);
            asm volatile("cp.async.cg.shared.global [%0], [%1], 16;"
                         :: "r"(PB + sw), "l"(xsrc + (size_t)r * CIN + c * 8));
        }
    }

    auto load_A = [&](int s, int kp) {
        uint32_t dA = sb + s * ASTAGE;
        const __half* wp = g_w + kp * COUT * CIN;
#pragma unroll
        for (int i = 0; i < 8; i++) {
            int r = rgrp + 32 * i;
            uint32_t sw = (uint32_t)r * 256u + (uint32_t)((c ^ (r & 7)) * 16);
            asm volatile("cp.async.cg.shared.global [%0], [%1], 16;"
                         :: "r"(dA + sw), "l"(wp + r * CIN + c * 8));
        }
        asm volatile("cp.async.commit_group;" ::: "memory");
    };

    load_A(0, 0);   // one group: patch + A0

    const uint32_t selA = (uint32_t)(l >> 4);
    const uint32_t selB = (uint32_t)((l >> 3) & 1);
    const int rowA0 = wm * 64 + (l & 15);
    int pr0[2];
#pragma unroll
    for (int nb = 0; nb < 2; nb++) {
        int n = wn * 32 + (l & 7) + ((l >> 4) << 3) + nb * 16;
        if (n > 123) n = 123;
        pr0[nb] = (n / WOUT) * WWID + (n % WOUT);
    }

    float acc[4][4][4];
#pragma unroll
    for (int a = 0; a < 4; a++)
#pragma unroll
        for (int bb = 0; bb < 4; bb++)
#pragma unroll
            for (int e = 0; e < 4; e++) acc[a][bb][e] = 0.f;

    uint32_t afr[2][4][4], bfr[2][2][4];

    for (int kp = 0; kp < 9; kp++) {
        asm volatile("cp.async.wait_group 0;" ::: "memory");
        __syncthreads();
        if (kp < 8) load_A((kp + 1) & 1, kp + 1);   // overlaps compute below

        const uint32_t A = sb + (kp & 1) * ASTAGE;
        const int kh = kp / 3, kw = kp - 3 * kh;
        const int shift = kh * WWID + kw;
        uint32_t prow[2], pbase[2];
#pragma unroll
        for (int nb = 0; nb < 2; nb++) {
            prow[nb]  = (uint32_t)(pr0[nb] + shift);
            pbase[nb] = PB + prow[nb] * 256u;
        }

        auto load_frags = [&](int j, int p) {
#pragma unroll
            for (int fm = 0; fm < 4; fm++) {
                int r = rowA0 + fm * 16;
                uint32_t ch = ((uint32_t)(2 * j) + selA) ^ (uint32_t)(r & 7);
                uint32_t ad = A + (uint32_t)r * 256u + ch * 16u;
                asm volatile(
                    "ldmatrix.sync.aligned.m8n8.x4.shared.b16 {%0,%1,%2,%3}, [%4];"
                    : "=r"(afr[p][fm][0]), "=r"(afr[p][fm][1]),
                      "=r"(afr[p][fm][2]), "=r"(afr[p][fm][3])
                    : "r"(ad));
            }
#pragma unroll
            for (int nb = 0; nb < 2; nb++) {
                uint32_t ch = ((uint32_t)(2 * j) + selB) ^ (prow[nb] & 7u);
                uint32_t ad = pbase[nb] + ch * 16u;
                asm volatile(
                    "ldmatrix.sync.aligned.m8n8.x4.shared.b16 {%0,%1,%2,%3}, [%4];"
                    : "=r"(bfr[p][nb][0]), "=r"(bfr[p][nb][1]),
                      "=r"(bfr[p][nb][2]), "=r"(bfr[p][nb][3])
                    : "r"(ad));
            }
        };

        load_frags(0, 0);
#pragma unroll
        for (int j = 0; j < 8; j++) {            // K=128 in 8 x k16
            const int p = j & 1;
            if (j < 7) load_frags(j + 1, p ^ 1);
#pragma unroll
            for (int fm = 0; fm < 4; fm++)
#pragma unroll
                for (int nf = 0; nf < 4; nf++) {
                    asm volatile(
                        "mma.sync.aligned.m16n8k16.row.col.f32.f16.f16.f32 "
                        "{%0,%1,%2,%3}, {%4,%5,%6,%7}, {%8,%9}, {%0,%1,%2,%3};"
                        : "+f"(acc[fm][nf][0]), "+f"(acc[fm][nf][1]),
                          "+f"(acc[fm][nf][2]), "+f"(acc[fm][nf][3])
                        : "r"(afr[p][fm][0]), "r"(afr[p][fm][1]),
                          "r"(afr[p][fm][2]), "r"(afr[p][fm][3]),
                          "r"(bfr[p][nf >> 1][(nf & 1) * 2]),
                          "r"(bfr[p][nf >> 1][(nf & 1) * 2 + 1]));
                }
        }
    }

    // ----- epilogue: direct NCHW fp32 stores (skip pad pixels n>=124)
#pragma unroll
    for (int fm = 0; fm < 4; fm++) {
        int m = wm * 64 + fm * 16 + (l >> 2);
        size_t mb = (size_t)(b * COUT + m) * PIX_PER_IMG;
#pragma unroll
        for (int nf = 0; nf < 4; nf++) {
            int n0 = wn * 32 + nf * 8 + (l & 3) * 2;
#pragma unroll
            for (int e = 0; e < 2; e++) {
                int n = n0 + e;
                if (n < 124) {
                    int ho = r0 + (n >= WOUT ? 1 : 0);
                    int wo = n - (n >= WOUT ? WOUT : 0);
                    size_t idx = mb + (size_t)ho * WOUT + wo;
                    out[idx]                              = acc[fm][nf][e];
                    out[idx + (size_t)8 * PIX_PER_IMG]    = acc[fm][nf][2 + e];
                }
            }
        }
    }
}

// ---------------------------------------------------------------------------
extern "C" void kernel_launch(void* const* d_in, const int* in_sizes, int n_in,
                              void* d_out, int out_size) {
    const float* x = (const float*)d_in[0];
    const float* W = (const float*)d_in[1];
    float* out = (float*)d_out;

    prep_all<<<XBLOCKS + WBLOCKS, 256>>>(x, W);

    cudaFuncSetAttribute(xorconv_main,
                         cudaFuncAttributeMaxDynamicSharedMemorySize, SMEM_BYTES);
    dim3 gm(HOUT / 2, BDIM);   // 31 row-pairs x 32 images
    xorconv_main<<<gm, 512, SMEM_BYTES>>>(out);
}

// round 12
// speedup vs baseline: 1.4367x; 1.4367x over previous
#include <cuda_runtime.h>
#include <cuda_fp16.h>
#include <cstdint>

// ---------------------------------------------------------------------------
// XORConv2d: out = conv_valid(x, 1-2W), x (32,128,64,64) f32, W (256,128,3,3)
// Implicit GEMM on mma.sync fp16/fp32. sm_103 plain target (no tcgen05).
// R12: exact R9 config (best verified: frags-first order, merged prep) + 
// j-skew for warps 8..15 (rotated K-step order) so the two warp groups'
// LDSM and HMMA phases interleave instead of bursting in lockstep.
// ---------------------------------------------------------------------------

#define BDIM   32
#define CIN    128
#define HH     64
#define WWID   64
#define COUT   256
#define HOUT   62
#define WOUT   62
#define PIX_PER_IMG (HOUT*WOUT)         // 3844

__device__ __half g_x[(size_t)BDIM * HH * WWID * CIN];   // NHWC fp16, 32 MB
__device__ __half g_w[9 * COUT * CIN];                   // (1-2W), [kp][co][cin]

static __device__ __forceinline__ uint32_t smem_u32(const void* p) {
    uint32_t a;
    asm("{ .reg .u64 t; cvta.to.shared.u64 t, %1; cvt.u32.u64 %0, t; }"
        : "=r"(a) : "l"(p));
    return a;
}

// ---------------------------------------------------------------------------
// Merged prep: blocks [0,8192) transpose x NCHW f32 -> NHWC f16 (full-sector
// packed half2 writes); blocks [8192, 8192+1152) build g_w = 1-2W.
// ---------------------------------------------------------------------------
#define XBLOCKS 8192
#define WBLOCKS ((COUT*CIN*9 + 255) / 256)    // 1152

__global__ void prep_all(const float* __restrict__ x,
                         const float* __restrict__ W) {
    if (blockIdx.x < XBLOCKS) {
        __shared__ float t[64][33];
        int bid = blockIdx.x;
        int bh  = bid & 2047;              // b*64 + h
        int rest = bid >> 11;              // 0..3
        int b  = bh >> 6, h = bh & 63;
        int c0 = (rest & 1) * 64;
        int w0 = (rest >> 1) * 32;
        int l  = threadIdx.x & 31, wy = threadIdx.x >> 5;   // 8 warps

        const float* src = x + ((size_t)(b * CIN + c0)) * (HH * WWID)
                             + h * WWID + w0;
#pragma unroll
        for (int i = 0; i < 8; i++)
            t[wy + 8 * i][l] = src[(size_t)(wy + 8 * i) * (HH * WWID) + l];
        __syncthreads();

#pragma unroll
        for (int i = 0; i < 4; i++) {
            int ww = wy + 8 * i;
            __half2 v = __floats2half2_rn(t[2 * l][ww], t[2 * l + 1][ww]);
            __half* drow = g_x + ((size_t)(bh * WWID) + w0 + ww) * CIN + c0;
            ((uint32_t*)drow)[l] = *(uint32_t*)&v;
        }
    } else {
        int idx = (blockIdx.x - XBLOCKS) * 256 + threadIdx.x;
        if (idx < COUT * CIN * 9) {
            int co  = idx / (CIN * 9);
            int r   = idx - co * (CIN * 9);
            int cin = r / 9;
            int kp  = r - cin * 9;
            g_w[(kp * COUT + co) * CIN + cin] =
                __float2half_rn(1.0f - 2.0f * W[idx]);
        }
    }
}

// ---------------------------------------------------------------------------
// Main: CTA = 256 co x 124 pixels (image b, output rows r0, r0+1).
// Patch = input rows r0..r0+3 (256 rows x 256B = 64KB), loaded once.
// A double-buffered over 9 kp, one barrier per kp; register frag dbuf.
// Warps 8..15 run the K-steps rotated by 4 (phase interleave).
// 16 warps: 4(M) x 4(N), warp tile 64x32. grid (31, 32), 512 threads.
// ---------------------------------------------------------------------------
#define ASTAGE 65536
#define SMEM_BYTES (2*65536 + 65536 + 2048)

__global__ void __launch_bounds__(512, 1)
xorconv_main(float* __restrict__ out) {
    extern __shared__ char smem[];
    const uint32_t sb = smem_u32(smem);
    const uint32_t PB = sb + 2 * ASTAGE;        // patch base

    const int tid = threadIdx.x;
    const int l   = tid & 31;
    const int w   = tid >> 5;          // 0..15
    const int wm  = w & 3;             // M group (64 co)
    const int wn  = w >> 2;            // N group (32 pix)
    const int b   = blockIdx.y;
    const int r0  = blockIdx.x * 2;    // first output row
    const int jskew = (w >= 8) ? 4 : 0;   // phase offset for upper warp group

    const int c    = tid & 15;         // 16B chunk in a 256B row
    const int rgrp = tid >> 4;         // 32 groups; rows r = rgrp + 32*i

    // Patch: 256 contiguous g_x rows starting at (b, r0, 0)
    {
        const __half* xsrc = g_x + ((size_t)(b * (HH * WWID) + r0 * WWID)) * CIN;
#pragma unroll
        for (int i = 0; i < 8; i++) {
            int r = rgrp + 32 * i;
            uint32_t sw = (uint32_t)r * 256u + (uint32_t)((c ^ (r & 7)) * 16);
            asm volatile("cp.async.cg.shared.global [%0], [%1], 16;"
                         :: "r"(PB + sw), "l"(xsrc + (size_t)r * CIN + c * 8));
        }
    }

    auto load_A = [&](int s, int kp) {
        uint32_t dA = sb + s * ASTAGE;
        const __half* wp = g_w + kp * COUT * CIN;
#pragma unroll
        for (int i = 0; i < 8; i++) {
            int r = rgrp + 32 * i;
            uint32_t sw = (uint32_t)r * 256u + (uint32_t)((c ^ (r & 7)) * 16);
            asm volatile("cp.async.cg.shared.global [%0], [%1], 16;"
                         :: "r"(dA + sw), "l"(wp + r * CIN + c * 8));
        }
        asm volatile("cp.async.commit_group;" ::: "memory");
    };

    load_A(0, 0);   // one group: patch + A0

    const uint32_t selA = (uint32_t)(l >> 4);
    const uint32_t selB = (uint32_t)((l >> 3) & 1);
    const int rowA0 = wm * 64 + (l & 15);
    int pr0[2];
#pragma unroll
    for (int nb = 0; nb < 2; nb++) {
        int n = wn * 32 + (l & 7) + ((l >> 4) << 3) + nb * 16;
        if (n > 123) n = 123;
        pr0[nb] = (n / WOUT) * WWID + (n % WOUT);
    }

    float acc[4][4][4];
#pragma unroll
    for (int a = 0; a < 4; a++)
#pragma unroll
        for (int bb = 0; bb < 4; bb++)
#pragma unroll
            for (int e = 0; e < 4; e++) acc[a][bb][e] = 0.f;

    uint32_t afr[2][4][4], bfr[2][2][4];

    for (int kp = 0; kp < 9; kp++) {
        asm volatile("cp.async.wait_group 0;" ::: "memory");
        __syncthreads();

        const uint32_t A = sb + (kp & 1) * ASTAGE;
        const int kh = kp / 3, kw = kp - 3 * kh;
        const int shift = kh * WWID + kw;
        uint32_t prow[2], pbase[2];
#pragma unroll
        for (int nb = 0; nb < 2; nb++) {
            prow[nb]  = (uint32_t)(pr0[nb] + shift);
            pbase[nb] = PB + prow[nb] * 256u;
        }

        auto load_frags = [&](int j, int p) {
#pragma unroll
            for (int fm = 0; fm < 4; fm++) {
                int r = rowA0 + fm * 16;
                uint32_t ch = ((uint32_t)(2 * j) + selA) ^ (uint32_t)(r & 7);
                uint32_t ad = A + (uint32_t)r * 256u + ch * 16u;
                asm volatile(
                    "ldmatrix.sync.aligned.m8n8.x4.shared.b16 {%0,%1,%2,%3}, [%4];"
                    : "=r"(afr[p][fm][0]), "=r"(afr[p][fm][1]),
                      "=r"(afr[p][fm][2]), "=r"(afr[p][fm][3])
                    : "r"(ad));
            }
#pragma unroll
            for (int nb = 0; nb < 2; nb++) {
                uint32_t ch = ((uint32_t)(2 * j) + selB) ^ (prow[nb] & 7u);
                uint32_t ad = pbase[nb] + ch * 16u;
                asm volatile(
                    "ldmatrix.sync.aligned.m8n8.x4.shared.b16 {%0,%1,%2,%3}, [%4];"
                    : "=r"(bfr[p][nb][0]), "=r"(bfr[p][nb][1]),
                      "=r"(bfr[p][nb][2]), "=r"(bfr[p][nb][3])
                    : "r"(ad));
            }
        };

        // Frags for this group's first K-step, then prefetch next A stage.
        load_frags(jskew, 0);
        if (kp < 8) load_A((kp + 1) & 1, kp + 1);   // overlaps compute below

#pragma unroll
        for (int jj = 0; jj < 8; jj++) {         // K=128 in 8 x k16 (rotated)
            const int p = jj & 1;
            const int j = (jj + jskew) & 7;
            if (jj < 7) load_frags((j + 1) & 7, p ^ 1);
#pragma unroll
            for (int fm = 0; fm < 4; fm++)
#pragma unroll
                for (int nf = 0; nf < 4; nf++) {
                    asm volatile(
                        "mma.sync.aligned.m16n8k16.row.col.f32.f16.f16.f32 "
                        "{%0,%1,%2,%3}, {%4,%5,%6,%7}, {%8,%9}, {%0,%1,%2,%3};"
                        : "+f"(acc[fm][nf][0]), "+f"(acc[fm][nf][1]),
                          "+f"(acc[fm][nf][2]), "+f"(acc[fm][nf][3])
                        : "r"(afr[p][fm][0]), "r"(afr[p][fm][1]),
                          "r"(afr[p][fm][2]), "r"(afr[p][fm][3]),
                          "r"(bfr[p][nf >> 1][(nf & 1) * 2]),
                          "r"(bfr[p][nf >> 1][(nf & 1) * 2 + 1]));
                }
        }
    }

    // ----- epilogue: direct NCHW fp32 stores (skip pad pixels n>=124)
#pragma unroll
    for (int fm = 0; fm < 4; fm++) {
        int m = wm * 64 + fm * 16 + (l >> 2);
        size_t mb = (size_t)(b * COUT + m) * PIX_PER_IMG;
#pragma unroll
        for (int nf = 0; nf < 4; nf++) {
            int n0 = wn * 32 + nf * 8 + (l & 3) * 2;
#pragma unroll
            for (int e = 0; e < 2; e++) {
                int n = n0 + e;
                if (n < 124) {
                    int ho = r0 + (n >= WOUT ? 1 : 0);
                    int wo = n - (n >= WOUT ? WOUT : 0);
                    size_t idx = mb + (size_t)ho * WOUT + wo;
                    out[idx]                              = acc[fm][nf][e];
                    out[idx + (size_t)8 * PIX_PER_IMG]    = acc[fm][nf][2 + e];
                }
            }
        }
    }
}

// ---------------------------------------------------------------------------
extern "C" void kernel_launch(void* const* d_in, const int* in_sizes, int n_in,
                              void* d_out, int out_size) {
    const float* x = (const float*)d_in[0];
    const float* W = (const float*)d_in[1];
    float* out = (float*)d_out;

    prep_all<<<XBLOCKS + WBLOCKS, 256>>>(x, W);

    cudaFuncSetAttribute(xorconv_main,
                         cudaFuncAttributeMaxDynamicSharedMemorySize, SMEM_BYTES);
    dim3 gm(HOUT / 2, BDIM);   // 31 row-pairs x 32 images
    xorconv_main<<<gm, 512, SMEM_BYTES>>>(out);
}

// round 13
// speedup vs baseline: 1.5063x; 1.0485x over previous
#include <cuda_runtime.h>
#include <cuda_fp16.h>
#include <cstdint>

// ---------------------------------------------------------------------------
// XORConv2d: out = conv_valid(x, 1-2W), x (32,128,64,64) f32, W (256,128,3,3)
// Implicit GEMM on mma.sync fp16/fp32. sm_103 plain target (no tcgen05).
// R13: CTA = 64co x 124px; ALL 9 A-tiles (144KB) + patch (64KB) resident in
// smem -> mainloop has NO barriers / NO cp.async waits: 72 straight j-steps.
// 8 warps (2Mx4N, warp tile 32x32), ~85 regs, real register frag dbuf.
// grid (31, 32, 4) = 3968 CTAs.
// ---------------------------------------------------------------------------

#define BDIM   32
#define CIN    128
#define HH     64
#define WWID   64
#define COUT   256
#define HOUT   62
#define WOUT   62
#define PIX_PER_IMG (HOUT*WOUT)         // 3844

__device__ __half g_x[(size_t)BDIM * HH * WWID * CIN];   // NHWC fp16, 32 MB
__device__ __half g_w[9 * COUT * CIN];                   // (1-2W), [kp][co][cin]

static __device__ __forceinline__ uint32_t smem_u32(const void* p) {
    uint32_t a;
    asm("{ .reg .u64 t; cvta.to.shared.u64 t, %1; cvt.u32.u64 %0, t; }"
        : "=r"(a) : "l"(p));
    return a;
}

// ---------------------------------------------------------------------------
// Merged prep: blocks [0,8192) transpose x NCHW f32 -> NHWC f16; rest g_w.
// ---------------------------------------------------------------------------
#define XBLOCKS 8192
#define WBLOCKS ((COUT*CIN*9 + 255) / 256)    // 1152

__global__ void prep_all(const float* __restrict__ x,
                         const float* __restrict__ W) {
    if (blockIdx.x < XBLOCKS) {
        __shared__ float t[64][33];
        int bid = blockIdx.x;
        int bh  = bid & 2047;              // b*64 + h
        int rest = bid >> 11;              // 0..3
        int b  = bh >> 6, h = bh & 63;
        int c0 = (rest & 1) * 64;
        int w0 = (rest >> 1) * 32;
        int l  = threadIdx.x & 31, wy = threadIdx.x >> 5;   // 8 warps

        const float* src = x + ((size_t)(b * CIN + c0)) * (HH * WWID)
                             + h * WWID + w0;
#pragma unroll
        for (int i = 0; i < 8; i++)
            t[wy + 8 * i][l] = src[(size_t)(wy + 8 * i) * (HH * WWID) + l];
        __syncthreads();

#pragma unroll
        for (int i = 0; i < 4; i++) {
            int ww = wy + 8 * i;
            __half2 v = __floats2half2_rn(t[2 * l][ww], t[2 * l + 1][ww]);
            __half* drow = g_x + ((size_t)(bh * WWID) + w0 + ww) * CIN + c0;
            ((uint32_t*)drow)[l] = *(uint32_t*)&v;
        }
    } else {
        int idx = (blockIdx.x - XBLOCKS) * 256 + threadIdx.x;
        if (idx < COUT * CIN * 9) {
            int co  = idx / (CIN * 9);
            int r   = idx - co * (CIN * 9);
            int cin = r / 9;
            int kp  = r - cin * 9;
            g_w[(kp * COUT + co) * CIN + cin] =
                __float2half_rn(1.0f - 2.0f * W[idx]);
        }
    }
}

// ---------------------------------------------------------------------------
// Main. smem: [0, 144K) A tiles kp0..8 (16KB each) | [144K, 208K) patch.
// Two-phase entry (kp0-2 ready first), then barrier-free compute.
// ---------------------------------------------------------------------------
#define AKP    16384                         // 64 rows x 256B per kp
#define PBOFF  (9*AKP)                       // 147456
#define SMEM_BYTES (PBOFF + 256*256)         // 213_ ... 147456+65536 = 212992

__global__ void __launch_bounds__(256, 1)
xorconv_main(float* __restrict__ out) {
    extern __shared__ char smem[];
    const uint32_t sb = smem_u32(smem);
    const uint32_t PB = sb + PBOFF;

    const int tid = threadIdx.x;
    const int l   = tid & 31;
    const int w   = tid >> 5;          // 0..7
    const int wm  = w & 1;             // M group (32 co)
    const int wn  = w >> 1;            // N group (32 px)
    const int b   = blockIdx.y;
    const int r0  = blockIdx.x * 2;    // first output row
    const int co_base = blockIdx.z * 64;

    const int c    = tid & 15;         // 16B chunk in a 256B row
    const int rgrp = tid >> 4;         // 16 groups

    // ---- Load phase ----
    // Patch: 256 contiguous g_x rows starting at (b, r0, 0); rows rgrp+16i.
    {
        const __half* xsrc = g_x + ((size_t)(b * (HH * WWID) + r0 * WWID)) * CIN;
#pragma unroll
        for (int i = 0; i < 16; i++) {
            int r = rgrp + 16 * i;
            uint32_t sw = (uint32_t)r * 256u + (uint32_t)((c ^ (r & 7)) * 16);
            asm volatile("cp.async.cg.shared.global [%0], [%1], 16;"
                         :: "r"(PB + sw), "l"(xsrc + (size_t)r * CIN + c * 8));
        }
    }
    // A tiles: 64 rows (co) x 256B per kp.
    auto load_Akp = [&](int kp) {
        uint32_t dA = sb + kp * AKP;
        const __half* wp = g_w + (kp * COUT + co_base) * CIN;
#pragma unroll
        for (int i = 0; i < 4; i++) {
            int r = rgrp + 16 * i;
            uint32_t sw = (uint32_t)r * 256u + (uint32_t)((c ^ (r & 7)) * 16);
            asm volatile("cp.async.cg.shared.global [%0], [%1], 16;"
                         :: "r"(dA + sw), "l"(wp + r * CIN + c * 8));
        }
    };
#pragma unroll
    for (int kp = 0; kp < 3; kp++) load_Akp(kp);
    asm volatile("cp.async.commit_group;" ::: "memory");   // G0: patch + A0-2
#pragma unroll
    for (int kp = 3; kp < 9; kp++) load_Akp(kp);
    asm volatile("cp.async.commit_group;" ::: "memory");   // G1: A3-8

    // ---- Per-lane constants ----
    const uint32_t selA = (uint32_t)(l >> 4);
    const uint32_t selB = (uint32_t)((l >> 3) & 1);
    const int rowA0 = wm * 32 + (l & 15);
    int pr0[2];
#pragma unroll
    for (int nb = 0; nb < 2; nb++) {
        int n = wn * 32 + (l & 7) + ((l >> 4) << 3) + nb * 16;
        if (n > 123) n = 123;
        pr0[nb] = (n / WOUT) * WWID + (n % WOUT);
    }

    float acc[2][4][4];
#pragma unroll
    for (int a = 0; a < 2; a++)
#pragma unroll
        for (int bb = 0; bb < 4; bb++)
#pragma unroll
            for (int e = 0; e < 4; e++) acc[a][bb][e] = 0.f;

    uint32_t afr[2][2][4], bfr[2][2][4];

    // ---- Compute one kp (8 j-steps, register frag dbuf, no barriers) ----
    auto run_kp = [&](int kp) {
        const uint32_t A = sb + kp * AKP;
        const int kh = kp / 3, kw = kp - 3 * kh;
        const int shift = kh * WWID + kw;
        uint32_t prow[2], pbase[2];
#pragma unroll
        for (int nb = 0; nb < 2; nb++) {
            prow[nb]  = (uint32_t)(pr0[nb] + shift);
            pbase[nb] = PB + prow[nb] * 256u;
        }

        auto load_frags = [&](int j, int p) {
#pragma unroll
            for (int fm = 0; fm < 2; fm++) {
                int r = rowA0 + fm * 16;
                uint32_t ch = ((uint32_t)(2 * j) + selA) ^ (uint32_t)(r & 7);
                uint32_t ad = A + (uint32_t)r * 256u + ch * 16u;
                asm volatile(
                    "ldmatrix.sync.aligned.m8n8.x4.shared.b16 {%0,%1,%2,%3}, [%4];"
                    : "=r"(afr[p][fm][0]), "=r"(afr[p][fm][1]),
                      "=r"(afr[p][fm][2]), "=r"(afr[p][fm][3])
                    : "r"(ad));
            }
#pragma unroll
            for (int nb = 0; nb < 2; nb++) {
                uint32_t ch = ((uint32_t)(2 * j) + selB) ^ (prow[nb] & 7u);
                uint32_t ad = pbase[nb] + ch * 16u;
                asm volatile(
                    "ldmatrix.sync.aligned.m8n8.x4.shared.b16 {%0,%1,%2,%3}, [%4];"
                    : "=r"(bfr[p][nb][0]), "=r"(bfr[p][nb][1]),
                      "=r"(bfr[p][nb][2]), "=r"(bfr[p][nb][3])
                    : "r"(ad));
            }
        };

        load_frags(0, 0);
#pragma unroll
        for (int j = 0; j < 8; j++) {
            const int p = j & 1;
            if (j < 7) load_frags(j + 1, p ^ 1);
#pragma unroll
            for (int fm = 0; fm < 2; fm++)
#pragma unroll
                for (int nf = 0; nf < 4; nf++) {
                    asm volatile(
                        "mma.sync.aligned.m16n8k16.row.col.f32.f16.f16.f32 "
                        "{%0,%1,%2,%3}, {%4,%5,%6,%7}, {%8,%9}, {%0,%1,%2,%3};"
                        : "+f"(acc[fm][nf][0]), "+f"(acc[fm][nf][1]),
                          "+f"(acc[fm][nf][2]), "+f"(acc[fm][nf][3])
                        : "r"(afr[p][fm][0]), "r"(afr[p][fm][1]),
                          "r"(afr[p][fm][2]), "r"(afr[p][fm][3]),
                          "r"(bfr[p][nf >> 1][(nf & 1) * 2]),
                          "r"(bfr[p][nf >> 1][(nf & 1) * 2 + 1]));
                }
        }
    };

    // Phase 1: patch + A0-2 resident
    asm volatile("cp.async.wait_group 1;" ::: "memory");
    __syncthreads();
    run_kp(0); run_kp(1); run_kp(2);

    // Phase 2: everything resident; barrier-free to the end
    asm volatile("cp.async.wait_group 0;" ::: "memory");
    __syncthreads();
    run_kp(3); run_kp(4); run_kp(5);
    run_kp(6); run_kp(7); run_kp(8);

    // ---- Epilogue: direct NCHW fp32 stores (skip pad pixels n>=124) ----
#pragma unroll
    for (int fm = 0; fm < 2; fm++) {
        int m = co_base + wm * 32 + fm * 16 + (l >> 2);
        size_t mb = (size_t)(b * COUT + m) * PIX_PER_IMG;
#pragma unroll
        for (int nf = 0; nf < 4; nf++) {
            int n0 = wn * 32 + nf * 8 + (l & 3) * 2;
#pragma unroll
            for (int e = 0; e < 2; e++) {
                int n = n0 + e;
                if (n < 124) {
                    int ho = r0 + (n >= WOUT ? 1 : 0);
                    int wo = n - (n >= WOUT ? WOUT : 0);
                    size_t idx = mb + (size_t)ho * WOUT + wo;
                    out[idx]                              = acc[fm][nf][e];
                    out[idx + (size_t)8 * PIX_PER_IMG]    = acc[fm][nf][2 + e];
                }
            }
        }
    }
}

// ---------------------------------------------------------------------------
extern "C" void kernel_launch(void* const* d_in, const int* in_sizes, int n_in,
                              void* d_out, int out_size) {
    const float* x = (const float*)d_in[0];
    const float* W = (const float*)d_in[1];
    float* out = (float*)d_out;

    prep_all<<<XBLOCKS + WBLOCKS, 256>>>(x, W);

    cudaFuncSetAttribute(xorconv_main,
                         cudaFuncAttributeMaxDynamicSharedMemorySize, SMEM_BYTES);
    dim3 gm(HOUT / 2, BDIM, 4);   // 31 row-pairs x 32 images x 4 co-groups
    xorconv_main<<<gm, 256, SMEM_BYTES>>>(out);
}

// round 14
// speedup vs baseline: 1.6210x; 1.0761x over previous
#include <cuda_runtime.h>
#include <cuda_fp16.h>
#include <cstdint>

// ---------------------------------------------------------------------------
// XORConv2d: out = conv_valid(x, 1-2W), x (32,128,64,64) f32, W (256,128,3,3)
// Implicit GEMM on mma.sync fp16/fp32. sm_103 plain target (no tcgen05).
// R14: 2 CTAs/SM for cross-CTA latency hiding. CTA = 128co x 124px, 256 thr,
// 8 warps (2Mx4N, warp 64x32 = best LDSM:mma ratio). Single 32KB A buffer +
// 64KB patch = 96KB smem/CTA -> 2 resident. ~108 regs, no demotion.
// grid (31, 32, 2) = 1984 CTAs.
// ---------------------------------------------------------------------------

#define BDIM   32
#define CIN    128
#define HH     64
#define WWID   64
#define COUT   256
#define HOUT   62
#define WOUT   62
#define PIX_PER_IMG (HOUT*WOUT)         // 3844

__device__ __half g_x[(size_t)BDIM * HH * WWID * CIN];   // NHWC fp16, 32 MB
__device__ __half g_w[9 * COUT * CIN];                   // (1-2W), [kp][co][cin]

static __device__ __forceinline__ uint32_t smem_u32(const void* p) {
    uint32_t a;
    asm("{ .reg .u64 t; cvta.to.shared.u64 t, %1; cvt.u32.u64 %0, t; }"
        : "=r"(a) : "l"(p));
    return a;
}

// ---------------------------------------------------------------------------
// Merged prep: blocks [0,8192) transpose x NCHW f32 -> NHWC f16 (full-sector
// packed half2 writes); blocks [8192, 8192+1152) build g_w = 1-2W.
// ---------------------------------------------------------------------------
#define XBLOCKS 8192
#define WBLOCKS ((COUT*CIN*9 + 255) / 256)    // 1152

__global__ void prep_all(const float* __restrict__ x,
                         const float* __restrict__ W) {
    if (blockIdx.x < XBLOCKS) {
        __shared__ float t[64][33];
        int bid = blockIdx.x;
        int bh  = bid & 2047;              // b*64 + h
        int rest = bid >> 11;              // 0..3
        int b  = bh >> 6, h = bh & 63;
        int c0 = (rest & 1) * 64;
        int w0 = (rest >> 1) * 32;
        int l  = threadIdx.x & 31, wy = threadIdx.x >> 5;   // 8 warps

        const float* src = x + ((size_t)(b * CIN + c0)) * (HH * WWID)
                             + h * WWID + w0;
#pragma unroll
        for (int i = 0; i < 8; i++)
            t[wy + 8 * i][l] = src[(size_t)(wy + 8 * i) * (HH * WWID) + l];
        __syncthreads();

#pragma unroll
        for (int i = 0; i < 4; i++) {
            int ww = wy + 8 * i;
            __half2 v = __floats2half2_rn(t[2 * l][ww], t[2 * l + 1][ww]);
            __half* drow = g_x + ((size_t)(bh * WWID) + w0 + ww) * CIN + c0;
            ((uint32_t*)drow)[l] = *(uint32_t*)&v;
        }
    } else {
        int idx = (blockIdx.x - XBLOCKS) * 256 + threadIdx.x;
        if (idx < COUT * CIN * 9) {
            int co  = idx / (CIN * 9);
            int r   = idx - co * (CIN * 9);
            int cin = r / 9;
            int kp  = r - cin * 9;
            g_w[(kp * COUT + co) * CIN + cin] =
                __float2half_rn(1.0f - 2.0f * W[idx]);
        }
    }
}

// ---------------------------------------------------------------------------
// Main. smem per CTA: [0, 32K) A buffer (128co x 256B) | [32K, 96K) patch.
// Per kp: wait+sync, compute, sync, load next A. The co-resident CTA on the
// same SM fills the tensor pipe during this CTA's load/barrier phases.
// ---------------------------------------------------------------------------
#define ABUF   32768
#define PBOFF  ABUF
#define SMEM_BYTES (ABUF + 65536)            // 98304 per CTA -> 2 CTAs/SM

__global__ void __launch_bounds__(256, 2)
xorconv_main(float* __restrict__ out) {
    extern __shared__ char smem[];
    const uint32_t sb = smem_u32(smem);
    const uint32_t PB = sb + PBOFF;

    const int tid = threadIdx.x;
    const int l   = tid & 31;
    const int w   = tid >> 5;          // 0..7
    const int wm  = w & 1;             // M group (64 co)
    const int wn  = w >> 1;            // N group (32 px)
    const int b   = blockIdx.y;
    const int r0  = blockIdx.x * 2;    // first output row
    const int co_base = blockIdx.z * 128;

    const int c    = tid & 15;         // 16B chunk in a 256B row
    const int rgrp = tid >> 4;         // 16 groups

    // ---- Patch: 256 contiguous g_x rows starting at (b, r0, 0) ----
    {
        const __half* xsrc = g_x + ((size_t)(b * (HH * WWID) + r0 * WWID)) * CIN;
#pragma unroll
        for (int i = 0; i < 16; i++) {
            int r = rgrp + 16 * i;
            uint32_t sw = (uint32_t)r * 256u + (uint32_t)((c ^ (r & 7)) * 16);
            asm volatile("cp.async.cg.shared.global [%0], [%1], 16;"
                         :: "r"(PB + sw), "l"(xsrc + (size_t)r * CIN + c * 8));
        }
    }

    // ---- A loader: 128 rows (co) x 256B for one kp ----
    auto load_A = [&](int kp) {
        const __half* wp = g_w + (kp * COUT + co_base) * CIN;
#pragma unroll
        for (int i = 0; i < 8; i++) {
            int r = rgrp + 16 * i;
            uint32_t sw = (uint32_t)r * 256u + (uint32_t)((c ^ (r & 7)) * 16);
            asm volatile("cp.async.cg.shared.global [%0], [%1], 16;"
                         :: "r"(sb + sw), "l"(wp + r * CIN + c * 8));
        }
        asm volatile("cp.async.commit_group;" ::: "memory");
    };

    load_A(0);   // one group: patch + A0

    // ---- Per-lane constants ----
    const uint32_t selA = (uint32_t)(l >> 4);
    const uint32_t selB = (uint32_t)((l >> 3) & 1);
    const int rowA0 = wm * 64 + (l & 15);
    int pr0[2];
#pragma unroll
    for (int nb = 0; nb < 2; nb++) {
        int n = wn * 32 + (l & 7) + ((l >> 4) << 3) + nb * 16;
        if (n > 123) n = 123;
        pr0[nb] = (n / WOUT) * WWID + (n % WOUT);
    }

    float acc[4][4][4];
#pragma unroll
    for (int a = 0; a < 4; a++)
#pragma unroll
        for (int bb = 0; bb < 4; bb++)
#pragma unroll
            for (int e = 0; e < 4; e++) acc[a][bb][e] = 0.f;

    for (int kp = 0; kp < 9; kp++) {
        asm volatile("cp.async.wait_group 0;" ::: "memory");
        __syncthreads();                       // A(kp) (+patch) resident

        const int kh = kp / 3, kw = kp - 3 * kh;
        const int shift = kh * WWID + kw;
        uint32_t prow[2], pbase[2];
#pragma unroll
        for (int nb = 0; nb < 2; nb++) {
            prow[nb]  = (uint32_t)(pr0[nb] + shift);
            pbase[nb] = PB + prow[nb] * 256u;
        }

#pragma unroll
        for (int j = 0; j < 8; j++) {          // K=128 in 8 x k16
            uint32_t a[4][4], bq[2][4];
#pragma unroll
            for (int fm = 0; fm < 4; fm++) {
                int r = rowA0 + ((fm & 1) ? 80 - 64 * wm * 0 : 0), rr;
                rr = rowA0 + fm * 16;          // rows wm*64 + fm*16 + lane
                uint32_t ch = ((uint32_t)(2 * j) + selA) ^ (uint32_t)(rr & 7);
                uint32_t ad = sb + (uint32_t)rr * 256u + ch * 16u;
                asm volatile(
                    "ldmatrix.sync.aligned.m8n8.x4.shared.b16 {%0,%1,%2,%3}, [%4];"
                    : "=r"(a[fm][0]), "=r"(a[fm][1]), "=r"(a[fm][2]), "=r"(a[fm][3])
                    : "r"(ad));
                (void)r;
            }
#pragma unroll
            for (int nb = 0; nb < 2; nb++) {
                uint32_t ch = ((uint32_t)(2 * j) + selB) ^ (prow[nb] & 7u);
                uint32_t ad = pbase[nb] + ch * 16u;
                asm volatile(
                    "ldmatrix.sync.aligned.m8n8.x4.shared.b16 {%0,%1,%2,%3}, [%4];"
                    : "=r"(bq[nb][0]), "=r"(bq[nb][1]), "=r"(bq[nb][2]), "=r"(bq[nb][3])
                    : "r"(ad));
            }
#pragma unroll
            for (int fm = 0; fm < 4; fm++)
#pragma unroll
                for (int nf = 0; nf < 4; nf++) {
                    asm volatile(
                        "mma.sync.aligned.m16n8k16.row.col.f32.f16.f16.f32 "
                        "{%0,%1,%2,%3}, {%4,%5,%6,%7}, {%8,%9}, {%0,%1,%2,%3};"
                        : "+f"(acc[fm][nf][0]), "+f"(acc[fm][nf][1]),
                          "+f"(acc[fm][nf][2]), "+f"(acc[fm][nf][3])
                        : "r"(a[fm][0]), "r"(a[fm][1]), "r"(a[fm][2]), "r"(a[fm][3]),
                          "r"(bq[nf >> 1][(nf & 1) * 2]),
                          "r"(bq[nf >> 1][(nf & 1) * 2 + 1]));
                }
        }

        __syncthreads();                       // all warps done with A(kp)
        if (kp < 8) load_A(kp + 1);            // overwrite is now safe
    }

    // ---- Epilogue: direct NCHW fp32 stores (skip pad pixels n>=124) ----
#pragma unroll
    for (int fm = 0; fm < 4; fm++) {
        int m = co_base + wm * 64 + fm * 16 + (l >> 2);
        size_t mb = (size_t)(b * COUT + m) * PIX_PER_IMG;
#pragma unroll
        for (int nf = 0; nf < 4; nf++) {
            int n0 = wn * 32 + nf * 8 + (l & 3) * 2;
#pragma unroll
            for (int e = 0; e < 2; e++) {
                int n = n0 + e;
                if (n < 124) {
                    int ho = r0 + (n >= WOUT ? 1 : 0);
                    int wo = n - (n >= WOUT ? WOUT : 0);
                    size_t idx = mb + (size_t)ho * WOUT + wo;
                    out[idx]                              = acc[fm][nf][e];
                    out[idx + (size_t)8 * PIX_PER_IMG]    = acc[fm][nf][2 + e];
                }
            }
        }
    }
}

// ---------------------------------------------------------------------------
extern "C" void kernel_launch(void* const* d_in, const int* in_sizes, int n_in,
                              void* d_out, int out_size) {
    const float* x = (const float*)d_in[0];
    const float* W = (const float*)d_in[1];
    float* out = (float*)d_out;

    prep_all<<<XBLOCKS + WBLOCKS, 256>>>(x, W);

    cudaFuncSetAttribute(xorconv_main,
                         cudaFuncAttributeMaxDynamicSharedMemorySize, SMEM_BYTES);
    dim3 gm(HOUT / 2, BDIM, 2);   // 31 row-pairs x 32 images x 2 co-halves
    xorconv_main<<<gm, 256, SMEM_BYTES>>>(out);
}